// round 1
// baseline (speedup 1.0000x reference)
#include <cuda_runtime.h>
#include <cstdint>

// Problem constants (fixed shapes per reference)
#define BROWS 4096
#define DDIM  4096
#define OROWS 4096
#define MBUCK 2048

// Scratch: sketches live in device globals (no allocation allowed)
__device__ float g_sketch_in[(size_t)BROWS * MBUCK]; // 32 MB
__device__ float g_sketch_w [(size_t)OROWS * MBUCK]; // 32 MB

// ---------------------------------------------------------------------------
// Sketch kernel: one block per row. Shared-memory accumulator + shared atomics.
// ---------------------------------------------------------------------------
__global__ __launch_bounds__(256) void sketch_kernel(
    const float* __restrict__ x,      // [rows, DDIM]
    const int*   __restrict__ hidx,   // [DDIM]
    const float* __restrict__ sgn,    // [DDIM]
    int which)                        // 0 -> g_sketch_in, 1 -> g_sketch_w
{
    __shared__ __align__(16) float acc[MBUCK];
    float* out = which ? g_sketch_w : g_sketch_in;

    const int row = blockIdx.x;
    const float4* xr = (const float4*)(x + (size_t)row * DDIM);
    const int4*   h4 = (const int4*)hidx;
    const float4* s4 = (const float4*)sgn;

    for (int i = threadIdx.x; i < MBUCK; i += 256) acc[i] = 0.0f;
    __syncthreads();

    #pragma unroll
    for (int it = 0; it < DDIM / 4 / 256; ++it) {
        int idx = it * 256 + threadIdx.x;
        float4 xv = xr[idx];
        int4   hv = h4[idx];
        float4 sv = s4[idx];
        atomicAdd(&acc[hv.x], xv.x * sv.x);
        atomicAdd(&acc[hv.y], xv.y * sv.y);
        atomicAdd(&acc[hv.z], xv.z * sv.z);
        atomicAdd(&acc[hv.w], xv.w * sv.w);
    }
    __syncthreads();

    float4* o4 = (float4*)(out + (size_t)row * MBUCK);
    const float4* a4 = (const float4*)acc;
    for (int i = threadIdx.x; i < MBUCK / 4; i += 256) o4[i] = a4[i];
}

// ---------------------------------------------------------------------------
// GEMM-NT: C[M,N] = A[M,K] * B[N,K]^T + bias,  M=N=4096, K=2048 (fp32)
// BM=BN=128, BK=16, 256 threads, 8x8 per thread, packed f32x2 FMA.
// ---------------------------------------------------------------------------
#define GM 4096
#define GN 4096
#define GK 2048
#define BM 128
#define BN 128
#define BK 16
#define PAD 4   // 132-float row stride: 528 B = 33*16 -> float4-aligned, bank-skewed

#define FMA_F32X2(d, a, b, c) \
    asm("fma.rn.f32x2 %0, %1, %2, %3;" : "=l"(d) : "l"(a), "l"(b), "l"(c))
#define PACK_DUP_F32X2(d, s) \
    asm("mov.b64 %0, {%1, %1};" : "=l"(d) : "f"(s))
#define UNPACK_F32X2_F(lo, hi, in) \
    asm("mov.b64 {%0, %1}, %2;" : "=f"(lo), "=f"(hi) : "l"(in))

__global__ __launch_bounds__(256) void gemm_nt_bias_kernel(
    const float* __restrict__ bias,
    float* __restrict__ C)
{
    __shared__ __align__(16) float As[BK][BM + PAD];
    __shared__ __align__(16) float Bs[BK][BN + PAD];

    const float* A = g_sketch_in;  // [GM, GK]
    const float* B = g_sketch_w;   // [GN, GK]

    const int tid = threadIdx.x;
    const int tx = tid % 16;       // n-direction (8 cols each)
    const int ty = tid / 16;       // m-direction (8 rows each)
    const int bm = blockIdx.y * BM;
    const int bn = blockIdx.x * BN;

    // global-load mapping: 64 rows x 16 k per half, two halves
    const int lr = tid / 4;            // 0..63
    const int lc = (tid % 4) * 4;      // 0,4,8,12

    unsigned long long acc[8][4];      // 8 rows x 4 f32x2 pairs (8 cols)
    #pragma unroll
    for (int i = 0; i < 8; ++i)
        #pragma unroll
        for (int j = 0; j < 4; ++j)
            acc[i][j] = 0ULL;

    const float* Ap0 = A + (size_t)(bm + lr)      * GK + lc;
    const float* Ap1 = A + (size_t)(bm + lr + 64) * GK + lc;
    const float* Bp0 = B + (size_t)(bn + lr)      * GK + lc;
    const float* Bp1 = B + (size_t)(bn + lr + 64) * GK + lc;

    for (int kt = 0; kt < GK; kt += BK) {
        float4 a0 = *(const float4*)(Ap0 + kt);
        float4 a1 = *(const float4*)(Ap1 + kt);
        float4 b0 = *(const float4*)(Bp0 + kt);
        float4 b1 = *(const float4*)(Bp1 + kt);

        __syncthreads();  // prior compute done before overwriting smem
        As[lc + 0][lr] = a0.x;  As[lc + 1][lr] = a0.y;
        As[lc + 2][lr] = a0.z;  As[lc + 3][lr] = a0.w;
        As[lc + 0][lr + 64] = a1.x;  As[lc + 1][lr + 64] = a1.y;
        As[lc + 2][lr + 64] = a1.z;  As[lc + 3][lr + 64] = a1.w;
        Bs[lc + 0][lr] = b0.x;  Bs[lc + 1][lr] = b0.y;
        Bs[lc + 2][lr] = b0.z;  Bs[lc + 3][lr] = b0.w;
        Bs[lc + 0][lr + 64] = b1.x;  Bs[lc + 1][lr + 64] = b1.y;
        Bs[lc + 2][lr + 64] = b1.z;  Bs[lc + 3][lr + 64] = b1.w;
        __syncthreads();

        #pragma unroll
        for (int k = 0; k < BK; ++k) {
            float4 av0 = *(const float4*)&As[k][ty * 8];
            float4 av1 = *(const float4*)&As[k][ty * 8 + 4];
            // b pairs read directly as packed 64-bit words (contiguous n-pairs)
            ulonglong2 bq0 = *(const ulonglong2*)&Bs[k][tx * 8];
            ulonglong2 bq1 = *(const ulonglong2*)&Bs[k][tx * 8 + 4];
            unsigned long long bp[4] = {bq0.x, bq0.y, bq1.x, bq1.y};
            float af[8] = {av0.x, av0.y, av0.z, av0.w,
                           av1.x, av1.y, av1.z, av1.w};
            #pragma unroll
            for (int i = 0; i < 8; ++i) {
                unsigned long long aa;
                PACK_DUP_F32X2(aa, af[i]);
                #pragma unroll
                for (int j = 0; j < 4; ++j)
                    FMA_F32X2(acc[i][j], aa, bp[j], acc[i][j]);
            }
        }
    }

    // epilogue: unpack, add bias, store
    #pragma unroll
    for (int i = 0; i < 8; ++i) {
        const int row = bm + ty * 8 + i;
        float* crow = C + (size_t)row * GN + bn + tx * 8;
        #pragma unroll
        for (int j = 0; j < 4; ++j) {
            float lo, hi;
            UNPACK_F32X2_F(lo, hi, acc[i][j]);
            const int col = bn + tx * 8 + 2 * j;
            float2 v;
            v.x = lo + __ldg(&bias[col]);
            v.y = hi + __ldg(&bias[col + 1]);
            *(float2*)(crow + 2 * j) = v;
        }
    }
}

// ---------------------------------------------------------------------------
// Launch
// ---------------------------------------------------------------------------
extern "C" void kernel_launch(void* const* d_in, const int* in_sizes, int n_in,
                              void* d_out, int out_size)
{
    const float* input  = (const float*)d_in[0];  // [4096, 4096]
    const float* weight = (const float*)d_in[1];  // [4096, 4096]
    const float* bias   = (const float*)d_in[2];  // [4096]
    const int*   hidx   = (const int*)d_in[3];    // [4096]
    const float* sgn    = (const float*)d_in[4];  // [4096]
    float* out = (float*)d_out;                   // [4096, 4096]

    sketch_kernel<<<BROWS, 256>>>(input,  hidx, sgn, 0);
    sketch_kernel<<<OROWS, 256>>>(weight, hidx, sgn, 1);

    dim3 grid(GN / BN, GM / BM);  // 32 x 32
    gemm_nt_bias_kernel<<<grid, 256>>>(bias, out);
}

// round 3
// speedup vs baseline: 2.8232x; 2.8232x over previous
#include <cuda_runtime.h>
#include <cuda_fp16.h>
#include <cstdint>

// ---------------------------------------------------------------------------
// Problem constants
// ---------------------------------------------------------------------------
#define BROWS 4096
#define DDIM  4096
#define OROWS 4096
#define MBUCK 2048

#define GM 4096
#define GN 4096
#define KP 6144            // extended K: [hi|hi|lo] x [hi|lo|hi]
#define BM 128
#define BN 128
#define BK 64
#define NKT (KP / BK)      // 96

// smem: 2 stages x (A 16KB + B 16KB)
#define A_TILE_B 16384
#define STAGE_B  32768
#define SMEM_TOTAL (2 * STAGE_B)

// ---------------------------------------------------------------------------
// Scratch panels (fp16, row-major [rows][6144])
// ---------------------------------------------------------------------------
__device__ __align__(16) __half g_A[(size_t)GM * KP];  // 48 MB
__device__ __align__(16) __half g_B[(size_t)GN * KP];  // 48 MB

// ---------------------------------------------------------------------------
// Sketch kernel: one block per row; shared-atomic scatter-add, then fp32 ->
// (fp16 hi, fp16 lo) split written into the extended-K panels.
//   A row: [hi @0, hi @2048, lo @4096]
//   B row: [hi @0, lo @2048, hi @4096]
// ---------------------------------------------------------------------------
__global__ __launch_bounds__(256) void sketch_kernel(
    const float* __restrict__ x,
    const int*   __restrict__ hidx,
    const float* __restrict__ sgn,
    int which)   // 0 -> A panel, 1 -> B panel
{
    __shared__ __align__(16) float acc[MBUCK];
    const int row = blockIdx.x;
    const float4* xr = (const float4*)(x + (size_t)row * DDIM);
    const int4*   h4 = (const int4*)hidx;
    const float4* s4 = (const float4*)sgn;

    for (int i = threadIdx.x; i < MBUCK; i += 256) acc[i] = 0.0f;
    __syncthreads();

    #pragma unroll
    for (int it = 0; it < DDIM / 4 / 256; ++it) {
        int idx = it * 256 + threadIdx.x;
        float4 xv = xr[idx];
        int4   hv = h4[idx];
        float4 sv = s4[idx];
        atomicAdd(&acc[hv.x], xv.x * sv.x);
        atomicAdd(&acc[hv.y], xv.y * sv.y);
        atomicAdd(&acc[hv.z], xv.z * sv.z);
        atomicAdd(&acc[hv.w], xv.w * sv.w);
    }
    __syncthreads();

    // each thread owns 8 buckets
    const int k0 = threadIdx.x * 8;
    uint32_t hw[4], lw[4];
    #pragma unroll
    for (int j = 0; j < 4; ++j) {
        float v0 = acc[k0 + 2 * j], v1 = acc[k0 + 2 * j + 1];
        __half h0 = __float2half_rn(v0);
        __half h1 = __float2half_rn(v1);
        __half l0 = __float2half_rn(v0 - __half2float(h0));
        __half l1 = __float2half_rn(v1 - __half2float(h1));
        __half2 hp = __halves2half2(h0, h1);
        __half2 lp = __halves2half2(l0, l1);
        hw[j] = *(uint32_t*)&hp;
        lw[j] = *(uint32_t*)&lp;
    }
    uint4 hv4 = make_uint4(hw[0], hw[1], hw[2], hw[3]);
    uint4 lv4 = make_uint4(lw[0], lw[1], lw[2], lw[3]);

    __half* base = (which ? g_B : g_A) + (size_t)row * KP + k0;
    if (which == 0) {
        *(uint4*)(base)          = hv4;   // hi
        *(uint4*)(base + 2048)   = hv4;   // hi
        *(uint4*)(base + 4096)   = lv4;   // lo
    } else {
        *(uint4*)(base)          = hv4;   // hi
        *(uint4*)(base + 2048)   = lv4;   // lo
        *(uint4*)(base + 4096)   = hv4;   // hi
    }
}

// ---------------------------------------------------------------------------
// GEMM-NT via mma.sync m16n8k16 fp16->fp32.
// C[4096,4096] = A'[4096,6144] * B'[4096,6144]^T + bias
// 8 warps (4M x 2N), warp tile 32x64, BK=64, 2-stage cp.async.
// ---------------------------------------------------------------------------
__device__ __forceinline__ uint32_t sm_u32(const void* p) {
    uint32_t r;
    asm("{ .reg .u64 t; cvta.to.shared.u64 t, %1; cvt.u32.u64 %0, t; }"
        : "=r"(r) : "l"(p));
    return r;
}

#define CP_ASYNC16(saddr, gaddr) \
    asm volatile("cp.async.cg.shared.global [%0], [%1], 16;" \
                 :: "r"(saddr), "l"(gaddr))
#define CP_COMMIT() asm volatile("cp.async.commit_group;")
#define CP_WAIT(n)  asm volatile("cp.async.wait_group %0;" :: "n"(n))

#define LDMATRIX_X4(r0, r1, r2, r3, addr) \
    asm volatile("ldmatrix.sync.aligned.m8n8.x4.shared.b16 {%0,%1,%2,%3}, [%4];" \
                 : "=r"(r0), "=r"(r1), "=r"(r2), "=r"(r3) : "r"(addr))

#define MMA_16816(d, a, b) \
    asm volatile("mma.sync.aligned.m16n8k16.row.col.f32.f16.f16.f32 " \
                 "{%0,%1,%2,%3}, {%4,%5,%6,%7}, {%8,%9}, {%0,%1,%2,%3};" \
                 : "+f"(d[0]), "+f"(d[1]), "+f"(d[2]), "+f"(d[3]) \
                 : "r"(a[0]), "r"(a[1]), "r"(a[2]), "r"(a[3]), \
                   "r"(b[0]), "r"(b[1]))

__global__ __launch_bounds__(256, 2) void gemm_kernel(
    const float* __restrict__ bias,
    float* __restrict__ C)
{
    extern __shared__ char smem[];
    const uint32_t sb = sm_u32(smem);
    const int tid  = threadIdx.x;
    const int wid  = tid >> 5;
    const int lane = tid & 31;
    const int wm = wid >> 1;           // 0..3
    const int wn = wid & 1;            // 0..1
    const int bm = blockIdx.y * BM;
    const int bn = blockIdx.x * BN;

    const __half* gA = g_A + (size_t)bm * KP;
    const __half* gB = g_B + (size_t)bn * KP;

    // load mapping: 8 threads per row (8 x 16B chunks), 32 rows per pass
    const int lr = tid >> 3;           // 0..31
    const int lc = tid & 7;            // chunk 0..7

    float acc[2][8][4];
    #pragma unroll
    for (int mi = 0; mi < 2; ++mi)
        #pragma unroll
        for (int ni = 0; ni < 8; ++ni)
            #pragma unroll
            for (int j = 0; j < 4; ++j) acc[mi][ni][j] = 0.0f;

    // precomputed smem store addresses (swizzled) for the 4 row-passes
    uint32_t s_store[2][4];  // [A/B][pass]
    #pragma unroll
    for (int p = 0; p < 4; ++p) {
        int r = p * 32 + lr;
        uint32_t off = (uint32_t)r * 128 + (uint32_t)((lc ^ (r & 7)) << 4);
        s_store[0][p] = sb + off;
        s_store[1][p] = sb + A_TILE_B + off;
    }

    // ldmatrix addresses (depend on k16 step & stage; precompute row parts)
    // A: row = wm*32 + mi*16 + (lane&15); kc base = lane>>4
    // B: n   = wn*64 + (lane>>4)*8 + (lane&7); kc base = (lane>>3)&1
    const int a_row0 = wm * 32 + (lane & 15);
    const int a_kcb  = lane >> 4;
    const int b_n0   = wn * 64 + ((lane >> 4) << 3) + (lane & 7);
    const int b_kcb  = (lane >> 3) & 1;

    #define LOAD_STAGE(s, kt)                                                  \
        do {                                                                   \
            const __half* ga = gA + (size_t)(kt) * BK;                         \
            const __half* gb = gB + (size_t)(kt) * BK;                         \
            uint32_t so = (uint32_t)(s) * STAGE_B;                             \
            _Pragma("unroll")                                                  \
            for (int p = 0; p < 4; ++p) {                                      \
                int r = p * 32 + lr;                                           \
                CP_ASYNC16(s_store[0][p] + so,                                 \
                           (uint64_t)(ga + (size_t)r * KP + lc * 8));          \
                CP_ASYNC16(s_store[1][p] + so,                                 \
                           (uint64_t)(gb + (size_t)r * KP + lc * 8));          \
            }                                                                  \
            CP_COMMIT();                                                       \
        } while (0)

    LOAD_STAGE(0, 0);

    for (int kt = 0; kt < NKT; ++kt) {
        const int s = kt & 1;
        if (kt + 1 < NKT) {
            LOAD_STAGE(s ^ 1, kt + 1);
            CP_WAIT(1);
        } else {
            CP_WAIT(0);
        }
        __syncthreads();

        const uint32_t sA = sb + (uint32_t)s * STAGE_B;
        const uint32_t sB = sA + A_TILE_B;

        #pragma unroll
        for (int k16 = 0; k16 < BK / 16; ++k16) {
            uint32_t a[2][4];
            #pragma unroll
            for (int mi = 0; mi < 2; ++mi) {
                int row = a_row0 + mi * 16;
                int kc = k16 * 2 + a_kcb;
                uint32_t addr = sA + (uint32_t)row * 128
                              + (uint32_t)((kc ^ (row & 7)) << 4);
                LDMATRIX_X4(a[mi][0], a[mi][1], a[mi][2], a[mi][3], addr);
            }
            uint32_t b[8][2];
            #pragma unroll
            for (int nj = 0; nj < 4; ++nj) {
                int n = b_n0 + nj * 16;
                int kc = k16 * 2 + b_kcb;
                uint32_t addr = sB + (uint32_t)n * 128
                              + (uint32_t)((kc ^ (n & 7)) << 4);
                LDMATRIX_X4(b[nj * 2][0], b[nj * 2][1],
                            b[nj * 2 + 1][0], b[nj * 2 + 1][1], addr);
            }
            #pragma unroll
            for (int mi = 0; mi < 2; ++mi)
                #pragma unroll
                for (int ni = 0; ni < 8; ++ni)
                    MMA_16816(acc[mi][ni], a[mi], b[ni]);
        }
        __syncthreads();
    }

    // epilogue: add bias, store fp32
    #pragma unroll
    for (int mi = 0; mi < 2; ++mi) {
        const int r0 = bm + wm * 32 + mi * 16 + (lane >> 2);
        #pragma unroll
        for (int ni = 0; ni < 8; ++ni) {
            const int col = bn + wn * 64 + ni * 8 + (lane & 3) * 2;
            const float b0 = __ldg(bias + col);
            const float b1 = __ldg(bias + col + 1);
            float2 v0 = make_float2(acc[mi][ni][0] + b0, acc[mi][ni][1] + b1);
            float2 v1 = make_float2(acc[mi][ni][2] + b0, acc[mi][ni][3] + b1);
            *(float2*)(C + (size_t)r0 * GN + col)       = v0;
            *(float2*)(C + (size_t)(r0 + 8) * GN + col) = v1;
        }
    }
}

// ---------------------------------------------------------------------------
// Launch
// ---------------------------------------------------------------------------
extern "C" void kernel_launch(void* const* d_in, const int* in_sizes, int n_in,
                              void* d_out, int out_size)
{
    const float* input  = (const float*)d_in[0];
    const float* weight = (const float*)d_in[1];
    const float* bias   = (const float*)d_in[2];
    const int*   hidx   = (const int*)d_in[3];
    const float* sgn    = (const float*)d_in[4];
    float* out = (float*)d_out;

    sketch_kernel<<<BROWS, 256>>>(input,  hidx, sgn, 0);
    sketch_kernel<<<OROWS, 256>>>(weight, hidx, sgn, 1);

    cudaFuncSetAttribute(gemm_kernel,
                         cudaFuncAttributeMaxDynamicSharedMemorySize, SMEM_TOTAL);
    dim3 grid(GN / BN, GM / BM);  // 32 x 32
    gemm_kernel<<<grid, 256, SMEM_TOTAL>>>(bias, out);
}